// round 2
// baseline (speedup 1.0000x reference)
#include <cuda_runtime.h>
#include <cstdint>
#include <math.h>

namespace {
constexpr int kB = 64, kT = 1024, kI = 512, kH = 1024, kKV = 1536;
constexpr int kNCTA = 128, kNTHR = 128, kKC = 64, kNCH = kKV / kKC; // 24
constexpr int SB_OFF = 32 * kKV;           // weights: 32 rows x 1536 f32
constexpr int SV_OFF = SB_OFF + 32;        // biases: 32 f32
constexpr int SV_FLOATS = kB * kKC;        // 4096 f32 per v buffer
constexpr int SMEM_BYTES = (SV_OFF + 2 * SV_FLOATS) * 4; // 229,504 B
}

__device__ float g_h[2][kB * kH];
__device__ int   g_arr[kT];

__global__ void lstm_init() {
    int i = blockIdx.x * blockDim.x + threadIdx.x;
    if (i < kT) g_arr[i] = 0;
    if (i < kB * kH) g_h[0][i] = 0.0f;
}

#define FMA2(d, a, b) asm("fma.rn.f32x2 %0, %1, %2, %0;" : "+l"(d) : "l"(a), "l"(b))

__device__ __forceinline__ float sigf(float x) { return 1.0f / (1.0f + expf(-x)); }
__device__ __forceinline__ float red2(unsigned long long a) {
    return __uint_as_float((unsigned)a) + __uint_as_float((unsigned)(a >> 32));
}

__global__ void __launch_bounds__(kNTHR, 1) lstm_kernel(
    const float* __restrict__ x,
    const float* __restrict__ Wf, const float* __restrict__ bf,
    const float* __restrict__ Wi, const float* __restrict__ bi,
    const float* __restrict__ Wo, const float* __restrict__ bo,
    const float* __restrict__ Wc, const float* __restrict__ bc,
    float* __restrict__ out)
{
    extern __shared__ float smem[];
    const int tid = threadIdx.x;
    const int cta = blockIdx.x;
    const int j0  = cta * 8;

    // ---- stage weights (32 rows x 1536) + biases into SMEM, once ----
    {
        const float* const Wp[4] = {Wf, Wi, Wo, Wc};
        for (int g = 0; g < 4; ++g)
            for (int jl = 0; jl < 8; ++jl) {
                const float* src = Wp[g] + (size_t)(j0 + jl) * kKV;
                float* dst = smem + (jl * 4 + g) * kKV;
                for (int k = tid; k < kKV; k += kNTHR) dst[k] = __ldg(src + k);
            }
        if (tid < 32) {
            const float* const Bp[4] = {bf, bi, bo, bc};
            smem[SB_OFF + tid] = __ldg(Bp[tid & 3] + j0 + (tid >> 2));
        }
    }
    __syncthreads();

    uint32_t smem_u32;
    asm("{ .reg .u64 t0; cvta.to.shared.u64 t0, %1; cvt.u32.u64 %0, t0; }"
        : "=r"(smem_u32) : "l"(smem));
    const uint32_t sv_u32 = smem_u32 + SV_OFF * 4;

    const int bq   = tid & 15;   // compute: batches 4*bq..4*bq+3
    const int jl   = tid >> 4;   // compute: hidden unit j0+jl
    const int lq   = tid & 15;   // loader: k-quad
    const int brow = tid >> 4;   // loader: b = rr*8 + brow

    float cstate[4] = {0.f, 0.f, 0.f, 0.f};
    float hlast[4]  = {0.f, 0.f, 0.f, 0.f};

    for (int t = 0; t < kT; ++t) {
        const float* __restrict__ hin  = g_h[t & 1];
        float* __restrict__       hout = g_h[(t & 1) ^ 1];

        unsigned long long acc[16];
        #pragma unroll
        for (int i = 0; i < 16; ++i) acc[i] = 0ull;

        float4 stg[8];
        // preload chunk 0 (pure x) into buffer 0
        #pragma unroll
        for (int rr = 0; rr < 8; ++rr) {
            int b = rr * 8 + brow;
            stg[rr] = __ldg((const float4*)(x + ((size_t)b * kT + t) * kI + 4 * lq));
        }
        #pragma unroll
        for (int rr = 0; rr < 8; ++rr) {
            int b = rr * 8 + brow;
            int cell = b * 16 + ((lq + (b >> 2)) & 15);
            *(float4*)(smem + SV_OFF + cell * 4) = stg[rr];
        }
        __syncthreads();

        for (int c = 0; c < kNCH; ++c) {
            const int p = c & 1;
            // prefetch chunk c+1
            if (c + 1 < kNCH) {
                const int k0n = (c + 1) * kKC;
                if (k0n < kI) {
                    #pragma unroll
                    for (int rr = 0; rr < 8; ++rr) {
                        int b = rr * 8 + brow;
                        stg[rr] = __ldg((const float4*)(x + ((size_t)b * kT + t) * kI + k0n + 4 * lq));
                    }
                } else {
                    const int kh = k0n - kI;
                    #pragma unroll
                    for (int rr = 0; rr < 8; ++rr) {
                        int b = rr * 8 + brow;
                        stg[rr] = __ldcg((const float4*)(hin + b * kH + kh + 4 * lq));
                    }
                }
            }
            // compute on buffer p
            {
                const int k0 = c * kKC;
                const uint32_t svb = sv_u32 + (uint32_t)p * (SV_FLOATS * 4);
                #pragma unroll 4
                for (int kq = 0; kq < 16; ++kq) {
                    unsigned long long w01[4], w23[4];
                    #pragma unroll
                    for (int g = 0; g < 4; ++g) {
                        uint32_t wa = smem_u32 +
                            (uint32_t)(((jl * 4 + g) * kKV + k0 + 4 * kq) << 2);
                        asm volatile("ld.shared.v2.b64 {%0,%1}, [%2];"
                            : "=l"(w01[g]), "=l"(w23[g]) : "r"(wa));
                    }
                    #pragma unroll
                    for (int m = 0; m < 4; ++m) {
                        const int b = 4 * bq + m;
                        uint32_t va = svb + (uint32_t)((b * 16 + ((kq + bq) & 15)) << 4);
                        unsigned long long v01, v23;
                        asm volatile("ld.shared.v2.b64 {%0,%1}, [%2];"
                            : "=l"(v01), "=l"(v23) : "r"(va));
                        #pragma unroll
                        for (int g = 0; g < 4; ++g) {
                            FMA2(acc[m * 4 + g], v01, w01[g]);
                            FMA2(acc[m * 4 + g], v23, w23[g]);
                        }
                    }
                }
            }
            // commit prefetched chunk to buffer p^1
            if (c + 1 < kNCH) {
                float* dst = smem + SV_OFF + ((c + 1) & 1) * SV_FLOATS;
                #pragma unroll
                for (int rr = 0; rr < 8; ++rr) {
                    int b = rr * 8 + brow;
                    int cell = b * 16 + ((lq + (b >> 2)) & 15);
                    *(float4*)(dst + cell * 4) = stg[rr];
                }
            }
            __syncthreads();
        }

        // epilogue: gates + state update
        #pragma unroll
        for (int m = 0; m < 4; ++m) {
            int b = 4 * bq + m;
            float sf = red2(acc[m * 4 + 0]) + smem[SB_OFF + jl * 4 + 0];
            float si = red2(acc[m * 4 + 1]) + smem[SB_OFF + jl * 4 + 1];
            float so = red2(acc[m * 4 + 2]) + smem[SB_OFF + jl * 4 + 2];
            float sc = red2(acc[m * 4 + 3]) + smem[SB_OFF + jl * 4 + 3];
            float f = sigf(sf), i2 = sigf(si), o = sigf(so), g2 = tanhf(sc);
            float cn = f * cstate[m] + i2 * g2;
            cstate[m] = cn;
            float hn = o * tanhf(cn);
            hlast[m] = hn;
            if (t < kT - 1) hout[b * kH + j0 + jl] = hn;
        }

        if (t < kT - 1) {
            __threadfence();
            __syncthreads();
            if (tid == 0) {
                atomicAdd(&g_arr[t], 1);
                while (atomicAdd(&g_arr[t], 0) < kNCTA) {}
            }
            __syncthreads();
        }
    }

    // final output: h then c, each [B, H]
    #pragma unroll
    for (int m = 0; m < 4; ++m) {
        int b = 4 * bq + m;
        out[b * kH + j0 + jl]            = hlast[m];
        out[kB * kH + b * kH + j0 + jl]  = cstate[m];
    }
}

extern "C" void kernel_launch(void* const* d_in, const int* in_sizes, int n_in,
                              void* d_out, int out_size)
{
    (void)in_sizes; (void)n_in; (void)out_size;
    const float* x  = (const float*)d_in[0];
    const float* Wf = (const float*)d_in[1];
    const float* bf = (const float*)d_in[2];
    const float* Wi = (const float*)d_in[3];
    const float* bi = (const float*)d_in[4];
    const float* Wo = (const float*)d_in[5];
    const float* bo = (const float*)d_in[6];
    const float* Wc = (const float*)d_in[7];
    const float* bc = (const float*)d_in[8];
    float* out = (float*)d_out;

    cudaFuncSetAttribute(lstm_kernel,
                         cudaFuncAttributeMaxDynamicSharedMemorySize, SMEM_BYTES);
    lstm_init<<<256, 256>>>();
    lstm_kernel<<<kNCTA, kNTHR, SMEM_BYTES>>>(x, Wf, bf, Wi, bi, Wo, bo, Wc, bc, out);
}

// round 4
// speedup vs baseline: 1.7178x; 1.7178x over previous
#include <cuda_runtime.h>
#include <cuda_bf16.h>
#include <cstdint>
#include <math.h>

// simpleLSTM B=64 T=1024 I=512 H=1024 — mma.sync bf16-2split persistent kernel.
// (tcgen05 is sm_103a-only; this bench compiles compute_103, so use HMMA.)

namespace {
constexpr int kB=64, kT=1024, kI=512, kH=1024;
constexpr int kNCTA=128, kNTHR=128;
constexpr int kNCH=24, kXCH=8;          // 24 k-chunks of 64; first 8 = x, rest = h
constexpr int ATILE=8192;               // 64 rows x 128B (one bf16 64-col chunk)
constexpr int HBUF=16*ATILE;            // 16 h-chunks per buffer
// SMEM byte offsets
constexpr int WHI=0;                    // 24 chunk-tiles x 4096B (32 rows x 128B)
constexpr int WLO=98304;
constexpr int ABUF=196608;              // A hi: ABUF + p*ATILE  (p=0,1)
constexpr int ALOF=16384;               // A lo: ABUF + ALOF + p*ATILE
constexpr int DOFF=196608;              // D 64x36 f32 (reused after last chunk)
constexpr int BIAS=229376;              // 32 f32
constexpr int SMEMB=229504;
}

__device__ unsigned char g_xt_hi[(size_t)kT*kXCH*ATILE];
__device__ unsigned char g_xt_lo[(size_t)kT*kXCH*ATILE];
__device__ unsigned char g_ht_hi[2*HBUF];
__device__ unsigned char g_ht_lo[2*HBUF];
__device__ int g_arr[kT];

__device__ __forceinline__ uint32_t smem_u32_of(const void* p) {
    uint32_t a;
    asm("{ .reg .u64 t0; cvta.to.shared.u64 t0, %1; cvt.u32.u64 %0, t0; }"
        : "=r"(a) : "l"(p));
    return a;
}
__device__ __forceinline__ uint32_t swz128(uint32_t off) {
    return off ^ ((off >> 3) & 0x70);
}
__device__ __forceinline__ float sigf(float x) { return 1.0f / (1.0f + expf(-x)); }

#define LDSM4(R, A) \
    asm volatile("ldmatrix.sync.aligned.m8n8.x4.shared.b16 {%0,%1,%2,%3}, [%4];" \
        : "=r"((R)[0]), "=r"((R)[1]), "=r"((R)[2]), "=r"((R)[3]) : "r"(A))

#define MMA16816(D, A, B0, B1) \
    asm volatile("mma.sync.aligned.m16n8k16.row.col.f32.bf16.bf16.f32 " \
        "{%0,%1,%2,%3}, {%4,%5,%6,%7}, {%8,%9}, {%0,%1,%2,%3};" \
        : "+f"((D)[0]), "+f"((D)[1]), "+f"((D)[2]), "+f"((D)[3]) \
        : "r"((A)[0]), "r"((A)[1]), "r"((A)[2]), "r"((A)[3]), "r"(B0), "r"(B1))

__global__ void lstm4_init() {
    int i = blockIdx.x * blockDim.x + threadIdx.x;
    if (i < kT) g_arr[i] = 0;
    if (i < (2*HBUF)/4) {
        ((uint32_t*)g_ht_hi)[i] = 0u;
        ((uint32_t*)g_ht_lo)[i] = 0u;
    }
}

// x split+swizzle precompute: block = t*8 + c
__global__ void __launch_bounds__(128) lstm4_xsplit(const float* __restrict__ x) {
    int bx = blockIdx.x;
    int t = bx >> 3, c = bx & 7;
    unsigned char* dhi = g_xt_hi + (size_t)bx * ATILE;
    unsigned char* dlo = g_xt_lo + (size_t)bx * ATILE;
    for (int i = threadIdx.x; i < 2048; i += 128) {
        int row = i >> 5, pr = i & 31;
        int k = c * 64 + pr * 2;
        float2 f = *(const float2*)(x + ((size_t)row * kT + t) * kI + k);
        __nv_bfloat16 h0 = __float2bfloat16(f.x);
        __nv_bfloat16 h1 = __float2bfloat16(f.y);
        __nv_bfloat162 hp; hp.x = h0; hp.y = h1;
        __nv_bfloat162 lp = __floats2bfloat162_rn(
            f.x - __bfloat162float(h0), f.y - __bfloat162float(h1));
        uint32_t off = swz128((uint32_t)(row * 128 + pr * 4));
        *(uint32_t*)(dhi + off) = *(uint32_t*)&hp;
        *(uint32_t*)(dlo + off) = *(uint32_t*)&lp;
    }
}

__global__ void __launch_bounds__(kNTHR, 1) lstm4_kernel(
    const float* __restrict__ Wf, const float* __restrict__ bf,
    const float* __restrict__ Wi, const float* __restrict__ bi,
    const float* __restrict__ Wo, const float* __restrict__ bo,
    const float* __restrict__ Wc, const float* __restrict__ bc,
    float* __restrict__ out)
{
    extern __shared__ unsigned char smem[];
    const uint32_t sb = smem_u32_of(smem);
    const int tid = threadIdx.x, lane = tid & 31, w = tid >> 5;
    const int cta = blockIdx.x, j0 = cta * 8;

    // ---- stage weights as bf16 hi/lo SW128 chunk tiles (once) ----
    {
        const float* const Wp[4] = {Wf, Wi, Wo, Wc};
        for (int r = 0; r < 32; ++r) {
            const float* src = Wp[r & 3] + (size_t)(j0 + (r >> 2)) * 1536;
            for (int kp = tid; kp < 768; kp += kNTHR) {
                int k = kp * 2;
                float f0 = __ldg(src + k), f1 = __ldg(src + k + 1);
                __nv_bfloat16 h0 = __float2bfloat16(f0);
                __nv_bfloat16 h1 = __float2bfloat16(f1);
                __nv_bfloat162 hp; hp.x = h0; hp.y = h1;
                __nv_bfloat162 lp = __floats2bfloat162_rn(
                    f0 - __bfloat162float(h0), f1 - __bfloat162float(h1));
                uint32_t off = swz128((uint32_t)((k >> 6) * 4096 + (r << 7) + ((k & 63) << 1)));
                *(uint32_t*)(smem + WHI + off) = *(uint32_t*)&hp;
                *(uint32_t*)(smem + WLO + off) = *(uint32_t*)&lp;
            }
        }
        if (tid < 32) {
            const float* const Bp[4] = {bf, bi, bo, bc};
            *(float*)(smem + BIAS + tid * 4) = __ldg(Bp[tid & 3] + j0 + (tid >> 2));
        }
    }
    __syncthreads();

    // ---- per-thread ldmatrix address components ----
    const int m0   = w * 16;
    const int rowA = m0 + (lane & 15);
    const uint32_t aRow = (uint32_t)rowA * 128;
    const int aXor = rowA & 7;
    const int aCB  = lane >> 4;                    // 0/1
    const int rowB = ((lane >> 4) << 3) + (lane & 7);
    const uint32_t bRow = (uint32_t)rowB * 128;
    const int bXor = rowB & 7;
    const int bCB  = (lane >> 3) & 1;

    // epilogue mapping: thread owns (b, jl = jh*4+u), u=0..3
    const int eb = tid & 63, jh = tid >> 6;
    float cs[4] = {0.f, 0.f, 0.f, 0.f};
    float hv[4];

    for (int t = 0; t < kT; ++t) {
        const unsigned char* hhi = g_ht_hi + (size_t)(t & 1) * HBUF;
        const unsigned char* hlo = g_ht_lo + (size_t)(t & 1) * HBUF;

        float acc[4][4];
        #pragma unroll
        for (int nt = 0; nt < 4; ++nt)
            #pragma unroll
            for (int e = 0; e < 4; ++e) acc[nt][e] = 0.0f;

        // preload chunk 0 (x hi/lo) and commit to buffer 0
        uint4 stg[8];
        {
            size_t tb = (size_t)(t * kXCH) * ATILE;
            const uint4* shi = (const uint4*)(g_xt_hi + tb);
            const uint4* slo = (const uint4*)(g_xt_lo + tb);
            #pragma unroll
            for (int i = 0; i < 4; ++i) {
                stg[i]     = __ldg(shi + tid + i * kNTHR);
                stg[i + 4] = __ldg(slo + tid + i * kNTHR);
            }
            uint4* dhi = (uint4*)(smem + ABUF);
            uint4* dlo = (uint4*)(smem + ABUF + ALOF);
            #pragma unroll
            for (int i = 0; i < 4; ++i) {
                dhi[tid + i * kNTHR] = stg[i];
                dlo[tid + i * kNTHR] = stg[i + 4];
            }
        }
        __syncthreads();

        for (int c = 0; c < kNCH; ++c) {
            const int p = c & 1;
            // prefetch chunk c+1 into registers
            if (c + 1 < kNCH) {
                if (c + 1 < kXCH) {
                    size_t tb = (size_t)(t * kXCH + c + 1) * ATILE;
                    const uint4* shi = (const uint4*)(g_xt_hi + tb);
                    const uint4* slo = (const uint4*)(g_xt_lo + tb);
                    #pragma unroll
                    for (int i = 0; i < 4; ++i) {
                        stg[i]     = __ldg(shi + tid + i * kNTHR);
                        stg[i + 4] = __ldg(slo + tid + i * kNTHR);
                    }
                } else {
                    size_t tb = (size_t)(c + 1 - kXCH) * ATILE;
                    const uint4* shi = (const uint4*)(hhi + tb);
                    const uint4* slo = (const uint4*)(hlo + tb);
                    #pragma unroll
                    for (int i = 0; i < 4; ++i) {
                        stg[i]     = __ldcg(shi + tid + i * kNTHR);
                        stg[i + 4] = __ldcg(slo + tid + i * kNTHR);
                    }
                }
            }
            // compute on buffer p
            {
                const uint32_t ahB = sb + ABUF + (uint32_t)p * ATILE;
                const uint32_t alB = ahB + ALOF;
                const uint32_t bhB = sb + WHI + (uint32_t)c * 4096;
                const uint32_t blB = bhB + (uint32_t)(WLO - WHI);
                #pragma unroll
                for (int ks = 0; ks < 4; ++ks) {
                    uint32_t ah[4], al[4], bh0[4], bh1[4], bl0[4], bl1[4];
                    const uint32_t ca = (uint32_t)(((2 * ks + aCB) ^ aXor) << 4);
                    const uint32_t cb = (uint32_t)(((2 * ks + bCB) ^ bXor) << 4);
                    LDSM4(ah, ahB + aRow + ca);
                    LDSM4(al, alB + aRow + ca);
                    LDSM4(bh0, bhB + bRow + cb);
                    LDSM4(bh1, bhB + bRow + cb + 2048);
                    LDSM4(bl0, blB + bRow + cb);
                    LDSM4(bl1, blB + bRow + cb + 2048);
                    MMA16816(acc[0], ah, bh0[0], bh0[1]);
                    MMA16816(acc[1], ah, bh0[2], bh0[3]);
                    MMA16816(acc[2], ah, bh1[0], bh1[1]);
                    MMA16816(acc[3], ah, bh1[2], bh1[3]);
                    MMA16816(acc[0], ah, bl0[0], bl0[1]);
                    MMA16816(acc[1], ah, bl0[2], bl0[3]);
                    MMA16816(acc[2], ah, bl1[0], bl1[1]);
                    MMA16816(acc[3], ah, bl1[2], bl1[3]);
                    MMA16816(acc[0], al, bh0[0], bh0[1]);
                    MMA16816(acc[1], al, bh0[2], bh0[3]);
                    MMA16816(acc[2], al, bh1[0], bh1[1]);
                    MMA16816(acc[3], al, bh1[2], bh1[3]);
                }
            }
            // commit prefetched chunk to buffer p^1
            if (c + 1 < kNCH) {
                uint4* dhi = (uint4*)(smem + ABUF + (size_t)(p ^ 1) * ATILE);
                uint4* dlo = (uint4*)(smem + ABUF + ALOF + (size_t)(p ^ 1) * ATILE);
                #pragma unroll
                for (int i = 0; i < 4; ++i) {
                    dhi[tid + i * kNTHR] = stg[i];
                    dlo[tid + i * kNTHR] = stg[i + 4];
                }
            }
            __syncthreads();
        }

        // ---- stage D (64 x 32, row stride 36 f32) to SMEM ----
        {
            float2* Dp = (float2*)(smem + DOFF);
            const int mA = m0 + (lane >> 2);
            #pragma unroll
            for (int nt = 0; nt < 4; ++nt) {
                int n = nt * 8 + (lane & 3) * 2;
                Dp[(mA * 36 + n) >> 1]       = make_float2(acc[nt][0], acc[nt][1]);
                Dp[((mA + 8) * 36 + n) >> 1] = make_float2(acc[nt][2], acc[nt][3]);
            }
        }
        __syncthreads();

        // ---- gates + state update: thread owns (eb, jl=jh*4+u) ----
        {
            const float* Dp = (const float*)(smem + DOFF);
            const float* Bb = (const float*)(smem + BIAS);
            #pragma unroll
            for (int u = 0; u < 4; ++u) {
                int jl = jh * 4 + u;
                const float* dr = Dp + eb * 36 + jl * 4;
                float sf = dr[0] + Bb[jl * 4 + 0];
                float si = dr[1] + Bb[jl * 4 + 1];
                float so = dr[2] + Bb[jl * 4 + 2];
                float sg = dr[3] + Bb[jl * 4 + 3];
                float f = sigf(sf), ii = sigf(si), o = sigf(so), g = tanhf(sg);
                float cn = f * cs[u] + ii * g;
                cs[u] = cn;
                hv[u] = o * tanhf(cn);
            }
            if (t < kT - 1) {
                unsigned char* whi = g_ht_hi + (size_t)((t & 1) ^ 1) * HBUF;
                unsigned char* wlo = g_ht_lo + (size_t)((t & 1) ^ 1) * HBUF;
                const int gc = j0 + jh * 4;          // first of 4 global columns
                const int hc = gc >> 6;              // h-chunk
                const int cell = (gc & 63) >> 3;
                uint32_t off = (uint32_t)(eb * 128 + ((cell ^ (eb & 7)) << 4) + (gc & 7) * 2);
                __nv_bfloat16 h0 = __float2bfloat16(hv[0]);
                __nv_bfloat16 h1 = __float2bfloat16(hv[1]);
                __nv_bfloat16 h2 = __float2bfloat16(hv[2]);
                __nv_bfloat16 h3 = __float2bfloat16(hv[3]);
                __nv_bfloat162 p0; p0.x = h0; p0.y = h1;
                __nv_bfloat162 p1; p1.x = h2; p1.y = h3;
                uint2 hiw = make_uint2(*(uint32_t*)&p0, *(uint32_t*)&p1);
                __nv_bfloat162 q0 = __floats2bfloat162_rn(
                    hv[0] - __bfloat162float(h0), hv[1] - __bfloat162float(h1));
                __nv_bfloat162 q1 = __floats2bfloat162_rn(
                    hv[2] - __bfloat162float(h2), hv[3] - __bfloat162float(h3));
                uint2 low = make_uint2(*(uint32_t*)&q0, *(uint32_t*)&q1);
                *(uint2*)(whi + (size_t)hc * ATILE + off) = hiw;
                *(uint2*)(wlo + (size_t)hc * ATILE + off) = low;
            } else {
                #pragma unroll
                for (int u = 0; u < 4; ++u) {
                    out[eb * kH + j0 + jh * 4 + u]           = hv[u];
                    out[kB * kH + eb * kH + j0 + jh * 4 + u] = cs[u];
                }
            }
        }

        if (t < kT - 1) {
            __threadfence();
            __syncthreads();
            if (tid == 0) {
                atomicAdd(&g_arr[t], 1);
                while (atomicAdd(&g_arr[t], 0) < kNCTA) {}
            }
            __syncthreads();
        }
    }
}

extern "C" void kernel_launch(void* const* d_in, const int* in_sizes, int n_in,
                              void* d_out, int out_size)
{
    (void)in_sizes; (void)n_in; (void)out_size;
    const float* x  = (const float*)d_in[0];
    const float* Wf = (const float*)d_in[1];
    const float* bf = (const float*)d_in[2];
    const float* Wi = (const float*)d_in[3];
    const float* bi = (const float*)d_in[4];
    const float* Wo = (const float*)d_in[5];
    const float* bo = (const float*)d_in[6];
    const float* Wc = (const float*)d_in[7];
    const float* bc = (const float*)d_in[8];
    float* out = (float*)d_out;

    cudaFuncSetAttribute(lstm4_kernel,
                         cudaFuncAttributeMaxDynamicSharedMemorySize, SMEMB);
    lstm4_init<<<256, 256>>>();
    lstm4_xsplit<<<kT * kXCH, 128>>>(x);
    lstm4_kernel<<<kNCTA, kNTHR, SMEMB>>>(Wf, bf, Wi, bi, Wo, bo, Wc, bc, out);
}

// round 5
// speedup vs baseline: 1.8086x; 1.0529x over previous
#include <cuda_runtime.h>
#include <cuda_bf16.h>
#include <cstdint>
#include <math.h>

// simpleLSTM B=64 T=1024 I=512 H=1024 — HMMA bf16-2split persistent kernel,
// cp.async 4-stage pipeline (K=32 chunks), register/shuffle epilogue,
// acquire-spin grid barrier hidden behind x-only chunks.

namespace {
constexpr int kB=64, kT=1024, kI=512, kH=1024;
constexpr int kNCTA=128, kNTHR=128;
constexpr int kNCH=48, kXCH=16;        // 48 K=32 chunks; first 16 = x, rest = h
constexpr int CTILE=4096;              // 64 rows x 64B (one K=32 tile, hi or lo)
constexpr int HBUFB=32*CTILE;          // 131072 B per parity (hi or lo)
// SMEM byte offsets
constexpr int WHI=0;                   // 24 weight tiles x 4096B (32 rows x 128B)
constexpr int WLO=98304;
constexpr int ABUF=196608;             // 4 stages x 8192 (hi 4K + lo 4K)
constexpr int BIAS=229376;             // 32 f32
constexpr int SMEMB=229504;
}

__device__ unsigned char g_xt_hi[(size_t)kT*kXCH*CTILE];
__device__ unsigned char g_xt_lo[(size_t)kT*kXCH*CTILE];
__device__ unsigned char g_ht_hi[2*HBUFB];
__device__ unsigned char g_ht_lo[2*HBUFB];
__device__ int g_arr[kT];

__device__ __forceinline__ uint32_t smem_u32_of(const void* p) {
    uint32_t a;
    asm("{ .reg .u64 t0; cvta.to.shared.u64 t0, %1; cvt.u32.u64 %0, t0; }"
        : "=r"(a) : "l"(p));
    return a;
}
__device__ __forceinline__ uint32_t swz128(uint32_t o) { return o ^ ((o >> 3) & 0x70); }
__device__ __forceinline__ uint32_t swz64(uint32_t o)  { return o ^ ((o >> 3) & 0x30); }
__device__ __forceinline__ float sigf(float x) { return 1.0f / (1.0f + expf(-x)); }
__device__ __forceinline__ void cp16(uint32_t d, const void* s) {
    asm volatile("cp.async.cg.shared.global [%0], [%1], 16;" :: "r"(d), "l"(s));
}

#define LDSM4(R, A) \
    asm volatile("ldmatrix.sync.aligned.m8n8.x4.shared.b16 {%0,%1,%2,%3}, [%4];" \
        : "=r"((R)[0]), "=r"((R)[1]), "=r"((R)[2]), "=r"((R)[3]) : "r"(A))

#define MMA16816(D, A, B0, B1) \
    asm volatile("mma.sync.aligned.m16n8k16.row.col.f32.bf16.bf16.f32 " \
        "{%0,%1,%2,%3}, {%4,%5,%6,%7}, {%8,%9}, {%0,%1,%2,%3};" \
        : "+f"((D)[0]), "+f"((D)[1]), "+f"((D)[2]), "+f"((D)[3]) \
        : "r"((A)[0]), "r"((A)[1]), "r"((A)[2]), "r"((A)[3]), "r"(B0), "r"(B1))

__global__ void lstm5_init() {
    int i = blockIdx.x * blockDim.x + threadIdx.x;
    if (i < kT) g_arr[i] = 0;
    if (i < (2*HBUFB)/4) {
        ((uint32_t*)g_ht_hi)[i] = 0u;
        ((uint32_t*)g_ht_lo)[i] = 0u;
    }
}

// x split+swizzle precompute: block = t*16 + c; 64 rows x 32 cols, SW64 tiles
__global__ void __launch_bounds__(128) lstm5_xsplit(const float* __restrict__ x) {
    int bx = blockIdx.x;
    int t = bx >> 4, c = bx & 15;
    unsigned char* dhi = g_xt_hi + (size_t)bx * CTILE;
    unsigned char* dlo = g_xt_lo + (size_t)bx * CTILE;
    for (int i = threadIdx.x; i < 1024; i += 128) {
        int row = i >> 4, pr = i & 15;
        int k = c * 32 + pr * 2;
        float2 f = *(const float2*)(x + ((size_t)row * kT + t) * kI + k);
        __nv_bfloat16 h0 = __float2bfloat16(f.x);
        __nv_bfloat16 h1 = __float2bfloat16(f.y);
        __nv_bfloat162 hp; hp.x = h0; hp.y = h1;
        __nv_bfloat162 lp = __floats2bfloat162_rn(
            f.x - __bfloat162float(h0), f.y - __bfloat162float(h1));
        uint32_t off = swz64((uint32_t)(row * 64 + pr * 4));
        *(uint32_t*)(dhi + off) = *(uint32_t*)&hp;
        *(uint32_t*)(dlo + off) = *(uint32_t*)&lp;
    }
}

__device__ __forceinline__ void issue_chunk(uint32_t sb, int tid, int tt, int cc) {
    if (tt < kT) {
        uint32_t dst = sb + ABUF + (uint32_t)(cc & 3) * 8192 + (uint32_t)tid * 16;
        const unsigned char *shi, *slo;
        if (cc < kXCH) {
            size_t o = ((size_t)tt * kXCH + cc) * CTILE;
            shi = g_xt_hi + o; slo = g_xt_lo + o;
        } else {
            size_t o = (size_t)(tt & 1) * HBUFB + (size_t)(cc - kXCH) * CTILE;
            shi = g_ht_hi + o; slo = g_ht_lo + o;
        }
        size_t so = (size_t)tid * 16;
        cp16(dst,        shi + so);
        cp16(dst + 2048, shi + so + 2048);
        cp16(dst + 4096, slo + so);
        cp16(dst + 6144, slo + so + 2048);
    }
    asm volatile("cp.async.commit_group;" ::: "memory");
}

__global__ void __launch_bounds__(kNTHR, 1) lstm5_kernel(
    const float* __restrict__ Wf, const float* __restrict__ bf,
    const float* __restrict__ Wi, const float* __restrict__ bi,
    const float* __restrict__ Wo, const float* __restrict__ bo,
    const float* __restrict__ Wc, const float* __restrict__ bc,
    float* __restrict__ out)
{
    extern __shared__ unsigned char smem[];
    const uint32_t sb = smem_u32_of(smem);
    const int tid = threadIdx.x, lane = tid & 31, w = tid >> 5;
    const int cta = blockIdx.x, j0 = cta * 8;

    // ---- stage weights as bf16 hi/lo SW128 K=64 tiles (once) ----
    {
        const float* const Wp[4] = {Wf, Wi, Wo, Wc};
        for (int r = 0; r < 32; ++r) {
            const float* src = Wp[r & 3] + (size_t)(j0 + (r >> 2)) * 1536;
            for (int kp = tid; kp < 768; kp += kNTHR) {
                int k = kp * 2;
                float f0 = __ldg(src + k), f1 = __ldg(src + k + 1);
                __nv_bfloat16 h0 = __float2bfloat16(f0);
                __nv_bfloat16 h1 = __float2bfloat16(f1);
                __nv_bfloat162 hp; hp.x = h0; hp.y = h1;
                __nv_bfloat162 lp = __floats2bfloat162_rn(
                    f0 - __bfloat162float(h0), f1 - __bfloat162float(h1));
                uint32_t off = swz128((uint32_t)((k >> 6) * 4096 + (r << 7) + ((k & 63) << 1)));
                *(uint32_t*)(smem + WHI + off) = *(uint32_t*)&hp;
                *(uint32_t*)(smem + WLO + off) = *(uint32_t*)&lp;
            }
        }
        if (tid < 32) {
            const float* const Bp[4] = {bf, bi, bo, bc};
            *(float*)(smem + BIAS + tid * 4) = __ldg(Bp[tid & 3] + j0 + (tid >> 2));
        }
    }
    __syncthreads();

    // ---- per-thread ldmatrix address components ----
    const int m0 = w * 16;
    const int rowA = m0 + (lane & 15);
    const uint32_t aRow = (uint32_t)rowA * 64;       // SW64 A tiles: 64B rows
    const int aXor2 = (rowA >> 1) & 3;
    const int aCB = lane >> 4;
    const int rowB = ((lane >> 4) << 3) + (lane & 7);
    const uint32_t bRow = (uint32_t)rowB * 128;      // SW128 weight tiles
    const int bXor = rowB & 7;
    const int bCB = (lane >> 3) & 1;

    // ---- epilogue ownership: thread owns (myrow, jl = 2*nt + jbit), nt=0..3 ----
    const int jbit = (lane & 3) >> 1;
    const int myrow = m0 + (lane >> 2) + ((lane & 1) << 3);
    const int hc = j0 >> 5;            // h-chunk this CTA writes
    const int gclb = (j0 & 31);        // column base within that chunk
    float bb[4][4];
    {
        const float* Bb = (const float*)(smem + BIAS);
        #pragma unroll
        for (int nt = 0; nt < 4; ++nt)
            #pragma unroll
            for (int g4 = 0; g4 < 4; ++g4)
                bb[nt][g4] = Bb[(2 * nt + jbit) * 4 + g4];
    }

    float cs[4] = {0.f, 0.f, 0.f, 0.f};

    // pipeline prologue: chunks (0,0), (0,1)
    issue_chunk(sb, tid, 0, 0);
    issue_chunk(sb, tid, 0, 1);

    for (int t = 0; t < kT; ++t) {
        float acc[4][4];
        #pragma unroll
        for (int nt = 0; nt < 4; ++nt)
            #pragma unroll
            for (int e = 0; e < 4; ++e) acc[nt][e] = 0.0f;

        for (int c = 0; c < kNCH; ++c) {
            // grid barrier: must complete before first h-chunk issue (c+2==16)
            if (c == 14 && t > 0) {
                if (tid == 0) {
                    uint32_t v;
                    do {
                        asm volatile("ld.acquire.gpu.global.u32 %0, [%1];"
                                     : "=r"(v) : "l"(g_arr + (t - 1)) : "memory");
                    } while (v < (uint32_t)kNCTA);
                }
                __syncthreads();
            }
            // issue chunk c+2 (may belong to next step)
            {
                int tt = t, cc = c + 2;
                if (cc >= kNCH) { tt++; cc -= kNCH; }
                issue_chunk(sb, tid, tt, cc);
            }
            asm volatile("cp.async.wait_group 2;" ::: "memory");
            __syncthreads();

            // compute chunk c
            const uint32_t aBase = sb + ABUF + (uint32_t)(c & 3) * 8192;
            const uint32_t bhB = sb + WHI + (uint32_t)(c >> 1) * 4096;
            const int ksg0 = (c & 1) * 2;
            #pragma unroll
            for (int ks = 0; ks < 2; ++ks) {
                uint32_t ah[4], al[4], bh0[4], bh1[4], bl0[4], bl1[4];
                uint32_t ca = (uint32_t)(((2 * ks + aCB) ^ aXor2) << 4);
                uint32_t cb = (uint32_t)(((2 * (ksg0 + ks) + bCB) ^ bXor) << 4);
                LDSM4(ah, aBase + aRow + ca);
                LDSM4(al, aBase + 4096 + aRow + ca);
                LDSM4(bh0, bhB + bRow + cb);
                LDSM4(bh1, bhB + bRow + cb + 2048);
                LDSM4(bl0, bhB + 98304 + bRow + cb);
                LDSM4(bl1, bhB + 98304 + bRow + cb + 2048);
                MMA16816(acc[0], ah, bh0[0], bh0[1]);
                MMA16816(acc[1], ah, bh0[2], bh0[3]);
                MMA16816(acc[2], ah, bh1[0], bh1[1]);
                MMA16816(acc[3], ah, bh1[2], bh1[3]);
                MMA16816(acc[0], ah, bl0[0], bl0[1]);
                MMA16816(acc[1], ah, bl0[2], bl0[3]);
                MMA16816(acc[2], ah, bl1[0], bl1[1]);
                MMA16816(acc[3], ah, bl1[2], bl1[3]);
                MMA16816(acc[0], al, bh0[0], bh0[1]);
                MMA16816(acc[1], al, bh0[2], bh0[3]);
                MMA16816(acc[2], al, bh1[0], bh1[1]);
                MMA16816(acc[3], al, bh1[2], bh1[3]);
            }
        }

        // ---- register/shuffle epilogue ----
        float hv[4];
        #pragma unroll
        for (int nt = 0; nt < 4; ++nt) {
            float p0 = __shfl_xor_sync(0xffffffffu, acc[nt][0], 1);
            float p1 = __shfl_xor_sync(0xffffffffu, acc[nt][1], 1);
            float p2 = __shfl_xor_sync(0xffffffffu, acc[nt][2], 1);
            float p3 = __shfl_xor_sync(0xffffffffu, acc[nt][3], 1);
            float gf, gi, go, gg;
            if (lane & 1) { gf = p2;           gi = p3;           go = acc[nt][2];  gg = acc[nt][3]; }
            else          { gf = acc[nt][0];   gi = acc[nt][1];   go = p0;          gg = p1; }
            float f  = sigf(gf + bb[nt][0]);
            float ii = sigf(gi + bb[nt][1]);
            float o  = sigf(go + bb[nt][2]);
            float g  = tanhf(gg + bb[nt][3]);
            float cn = f * cs[nt] + ii * g;
            cs[nt] = cn;
            hv[nt] = o * tanhf(cn);
        }

        if (t < kT - 1) {
            unsigned char* whi = g_ht_hi + (size_t)((t & 1) ^ 1) * HBUFB + (size_t)hc * CTILE;
            unsigned char* wlo = g_ht_lo + (size_t)((t & 1) ^ 1) * HBUFB + (size_t)hc * CTILE;
            #pragma unroll
            for (int nt = 0; nt < 4; ++nt) {
                int jl = 2 * nt + jbit;
                uint32_t off = swz64((uint32_t)(myrow * 64 + (gclb + jl) * 2));
                __nv_bfloat16 hb = __float2bfloat16(hv[nt]);
                *(__nv_bfloat16*)(whi + off) = hb;
                *(__nv_bfloat16*)(wlo + off) =
                    __float2bfloat16(hv[nt] - __bfloat162float(hb));
            }
            __threadfence();
            __syncthreads();
            if (tid == 0) atomicAdd(g_arr + t, 1);
        } else {
            #pragma unroll
            for (int nt = 0; nt < 4; ++nt) {
                int jl = 2 * nt + jbit;
                out[myrow * kH + j0 + jl]            = hv[nt];
                out[kB * kH + myrow * kH + j0 + jl]  = cs[nt];
            }
        }
    }
}

extern "C" void kernel_launch(void* const* d_in, const int* in_sizes, int n_in,
                              void* d_out, int out_size)
{
    (void)in_sizes; (void)n_in; (void)out_size;
    const float* x  = (const float*)d_in[0];
    const float* Wf = (const float*)d_in[1];
    const float* bf = (const float*)d_in[2];
    const float* Wi = (const float*)d_in[3];
    const float* bi = (const float*)d_in[4];
    const float* Wo = (const float*)d_in[5];
    const float* bo = (const float*)d_in[6];
    const float* Wc = (const float*)d_in[7];
    const float* bc = (const float*)d_in[8];
    float* out = (float*)d_out;

    cudaFuncSetAttribute(lstm5_kernel,
                         cudaFuncAttributeMaxDynamicSharedMemorySize, SMEMB);
    lstm5_init<<<256, 256>>>();
    lstm5_xsplit<<<kT * kXCH, 128>>>(x);
    lstm5_kernel<<<kNCTA, kNTHR, SMEMB>>>(Wf, bf, Wi, bi, Wo, bo, Wc, bc, out);
}

// round 6
// speedup vs baseline: 3.0040x; 1.6609x over previous
#include <cuda_runtime.h>
#include <cuda_bf16.h>
#include <cstdint>
#include <math.h>

// simpleLSTM B=64 T=1024 I=512 H=1024 — HMMA bf16-2split persistent kernel v6.
// A fragments loaded global->registers (no smem for A, no cp.async, no per-chunk
// syncs). 8 warps: K-split x2 groups, 4 M-slices each. B (weights) static in
// SMEM, LDSM only. Per-step: 2 syncthreads (acc reduction) + JIT grid barrier.

namespace {
constexpr int kB=64, kT=1024, kI=512, kH=1024;
constexpr int kNCTA=128, kNTHR=256;
constexpr int kNCH=48, kXCH=16;
constexpr int BLOB=8192;               // per-chunk A fragment blob (hi+lo)
constexpr int WHI=0, WLO=98304;        // weights: 24 tiles x 4096B, hi/lo
constexpr int ACC0=196608;             // [2 groups][64][37] f32
constexpr int ACCSTR=37;
constexpr int ACCSZ=64*ACCSTR*4;       // 9472
constexpr int SMEMB=ACC0+2*ACCSZ;      // 215552
}

__device__ unsigned char g_xt[(size_t)kT*16*BLOB];   // 128 MB x-fragment blobs
__device__ unsigned char g_ht[32*BLOB];              // 2 parities x 16 chunks
__device__ int g_arr[kT];

__device__ __forceinline__ uint32_t smem_u32_of(const void* p) {
    uint32_t a;
    asm("{ .reg .u64 t0; cvta.to.shared.u64 t0, %1; cvt.u32.u64 %0, t0; }"
        : "=r"(a) : "l"(p));
    return a;
}
__device__ __forceinline__ uint32_t swz128(uint32_t o) { return o ^ ((o >> 3) & 0x70); }
__device__ __forceinline__ float sigf(float x) { return 1.0f / (1.0f + expf(-x)); }

#define LDSM4(R, A) \
    asm volatile("ldmatrix.sync.aligned.m8n8.x4.shared.b16 {%0,%1,%2,%3}, [%4];" \
        : "=r"((R)[0]), "=r"((R)[1]), "=r"((R)[2]), "=r"((R)[3]) : "r"(A))

#define MMA16816(D, A, B0, B1) \
    asm volatile("mma.sync.aligned.m16n8k16.row.col.f32.bf16.bf16.f32 " \
        "{%0,%1,%2,%3}, {%4,%5,%6,%7}, {%8,%9}, {%0,%1,%2,%3};" \
        : "+f"((D)[0]), "+f"((D)[1]), "+f"((D)[2]), "+f"((D)[3]) \
        : "r"((A)[0]), "r"((A)[1]), "r"((A)[2]), "r"((A)[3]), "r"(B0), "r"(B1))

__global__ void lstm6_init() {
    int i = blockIdx.x * blockDim.x + threadIdx.x;
    if (i < kT) g_arr[i] = 0;
    if (i < (int)(sizeof(g_ht) / 16)) {
        uint4 z = make_uint4(0u, 0u, 0u, 0u);
        ((uint4*)g_ht)[i] = z;
    }
}

// Build x fragment blobs: block = t*16 + c. Blob layout per (slice s, ks):
// hi: s*2048 + ks*512 + lane*16 + r*4 ; lo at +1024.
// Frag element (lane,r,e): row = s*16+(lane>>2)+8*(r&1),
//                          col = ks*16+8*(r>>1)+(lane&3)*2+e.
__global__ void __launch_bounds__(128) lstm6_xsplit(const float* __restrict__ x) {
    __shared__ float xt[64 * 32];
    const int bx = blockIdx.x, t = bx >> 4, c = bx & 15, tid = threadIdx.x;
    #pragma unroll
    for (int v = 0; v < 4; ++v) {
        int idx = tid + v * 128;            // float4 index
        int b = idx >> 3, ko = (idx & 7) * 4;
        float4 f = *(const float4*)(x + ((size_t)b * kT + t) * kI + c * 32 + ko);
        *(float4*)(xt + b * 32 + ko) = f;
    }
    __syncthreads();
    const int s = tid >> 5, ks = (tid >> 4) & 1, l2 = tid & 15;
    unsigned char* base = g_xt + (size_t)bx * BLOB + s * 2048 + ks * 512;
    #pragma unroll
    for (int dl = 0; dl < 2; ++dl) {
        int l = l2 * 2 + dl;
        uint32_t hi[4], lo[4];
        #pragma unroll
        for (int r = 0; r < 4; ++r) {
            int row = s * 16 + (l >> 2) + 8 * (r & 1);
            int col = ks * 16 + 8 * (r >> 1) + (l & 3) * 2;
            float f0 = xt[row * 32 + col], f1 = xt[row * 32 + col + 1];
            __nv_bfloat16 h0 = __float2bfloat16(f0);
            __nv_bfloat16 h1 = __float2bfloat16(f1);
            __nv_bfloat162 hp; hp.x = h0; hp.y = h1;
            __nv_bfloat162 lp = __floats2bfloat162_rn(
                f0 - __bfloat162float(h0), f1 - __bfloat162float(h1));
            hi[r] = *(uint32_t*)&hp;
            lo[r] = *(uint32_t*)&lp;
        }
        *(uint4*)(base + l * 16)        = make_uint4(hi[0], hi[1], hi[2], hi[3]);
        *(uint4*)(base + 1024 + l * 16) = make_uint4(lo[0], lo[1], lo[2], lo[3]);
    }
}

__device__ __forceinline__ const unsigned char* ablob(int t, int c, int s) {
    if (c < kXCH) return g_xt + (((size_t)(t * 16 + c)) << 13) + s * 2048;
    return g_ht + (((size_t)((t & 1) * 16 + (c - kXCH))) << 13) + s * 2048;
}
__device__ __forceinline__ void lda(uint4* a, const unsigned char* p, int lane) {
    a[0] = __ldcg((const uint4*)(p + lane * 16));          // hi ks0
    a[1] = __ldcg((const uint4*)(p + 512 + lane * 16));    // hi ks1
    a[2] = __ldcg((const uint4*)(p + 1024 + lane * 16));   // lo ks0
    a[3] = __ldcg((const uint4*)(p + 1536 + lane * 16));   // lo ks1
}

__global__ void __launch_bounds__(kNTHR, 1) lstm6_kernel(
    const float* __restrict__ Wf, const float* __restrict__ bf,
    const float* __restrict__ Wi, const float* __restrict__ bi,
    const float* __restrict__ Wo, const float* __restrict__ bo,
    const float* __restrict__ Wc, const float* __restrict__ bc,
    float* __restrict__ out)
{
    extern __shared__ unsigned char smem[];
    const uint32_t sb = smem_u32_of(smem);
    const int tid = threadIdx.x, lane = tid & 31, w = tid >> 5;
    const int g = w >> 2, s = w & 3;          // k-group, m-slice
    const int cta = blockIdx.x, j0 = cta * 8;

    // ---- stage weights bf16 hi/lo SW128 K=64 tiles (once) ----
    {
        const float* const Wp[4] = {Wf, Wi, Wo, Wc};
        for (int r = 0; r < 32; ++r) {
            const float* src = Wp[r & 3] + (size_t)(j0 + (r >> 2)) * 1536;
            for (int kp = tid; kp < 768; kp += kNTHR) {
                int k = kp * 2;
                float f0 = __ldg(src + k), f1 = __ldg(src + k + 1);
                __nv_bfloat16 h0 = __float2bfloat16(f0);
                __nv_bfloat16 h1 = __float2bfloat16(f1);
                __nv_bfloat162 hp; hp.x = h0; hp.y = h1;
                __nv_bfloat162 lp = __floats2bfloat162_rn(
                    f0 - __bfloat162float(h0), f1 - __bfloat162float(h1));
                uint32_t off = swz128((uint32_t)((k >> 6) * 4096 + (r << 7) + ((k & 63) << 1)));
                *(uint32_t*)(smem + WHI + off) = *(uint32_t*)&hp;
                *(uint32_t*)(smem + WLO + off) = *(uint32_t*)&lp;
            }
        }
    }

    // B ldmatrix addressing (same as verified r5 path)
    const int rowB = ((lane >> 4) << 3) + (lane & 7);
    const uint32_t bRow = (uint32_t)rowB * 128;
    const int bXor = rowB & 7;
    const int bCB = (lane >> 3) & 1;

    // D staging
    const int m0 = s * 16;
    const int mA = m0 + (lane >> 2), cA = (lane & 3) * 2;
    float* abuf = (float*)(smem + ACC0 + g * ACCSZ);

    // epilogue ownership: (eb, units jl0=ej*2, jl0+1)
    const int eb = tid & 63, ej = tid >> 6;
    float bb[2][4];
    {
        const float* const Bp[4] = {bf, bi, bo, bc};
        #pragma unroll
        for (int u = 0; u < 2; ++u)
            #pragma unroll
            for (int g2 = 0; g2 < 4; ++g2)
                bb[u][g2] = __ldg(Bp[g2] + j0 + ej * 2 + u);
    }
    // h fragment write address (constant parts)
    const int jl = ej * 2;
    const int colh = (j0 & 31) + jl;
    const int s2 = eb >> 4, ri16 = eb & 15;
    const int lane2 = (ri16 & 7) * 4 + ((colh & 7) >> 1);
    const int r2 = (ri16 >> 3) + 2 * ((colh & 15) >> 3);
    const int ks2 = (colh >> 4) & 1;
    const size_t hoff = (size_t)s2 * 2048 + ks2 * 512 + lane2 * 16 + r2 * 4;
    const size_t hcsel = (size_t)((j0 >> 5) & 31) << 13;   // chunk within parity

    float cs[2] = {0.f, 0.f};
    __syncthreads();

    uint4 ap[3][4];
    lda(ap[0], ablob(0, g, s), lane);
    lda(ap[1], ablob(0, 2 + g, s), lane);
    lda(ap[2], ablob(0, 4 + g, s), lane);

    for (int t = 0; t < kT; ++t) {
        float acc[4][4];
        #pragma unroll
        for (int nt = 0; nt < 4; ++nt)
            #pragma unroll
            for (int e = 0; e < 4; ++e) acc[nt][e] = 0.0f;

        #pragma unroll 3
        for (int i = 0; i < 24; ++i) {
            if (t > 0 && i == 5) {           // JIT grid barrier before first h issue
                uint32_t v;
                do {
                    asm volatile("ld.acquire.gpu.global.u32 %0, [%1];"
                                 : "=r"(v) : "l"(g_arr + (t - 1)) : "memory");
                } while (v < (uint32_t)kNCTA);
            }
            const int c = 2 * i + g;
            const uint32_t bhB = sb + WHI + (uint32_t)(c >> 1) * 4096;
            const int ksg0 = (c & 1) * 2;
            #pragma unroll
            for (int ks = 0; ks < 2; ++ks) {
                uint32_t bh0[4], bh1[4], bl0[4], bl1[4];
                uint32_t cb = (uint32_t)(((2 * (ksg0 + ks) + bCB) ^ bXor) << 4);
                LDSM4(bh0, bhB + bRow + cb);
                LDSM4(bh1, bhB + bRow + cb + 2048);
                LDSM4(bl0, bhB + (WLO - WHI) + bRow + cb);
                LDSM4(bl1, bhB + (WLO - WHI) + bRow + cb + 2048);
                const uint32_t* ah = (const uint32_t*)&ap[i % 3][ks];
                const uint32_t* al = (const uint32_t*)&ap[i % 3][2 + ks];
                MMA16816(acc[0], ah, bh0[0], bh0[1]);
                MMA16816(acc[1], ah, bh0[2], bh0[3]);
                MMA16816(acc[2], ah, bh1[0], bh1[1]);
                MMA16816(acc[3], ah, bh1[2], bh1[3]);
                MMA16816(acc[0], ah, bl0[0], bl0[1]);
                MMA16816(acc[1], ah, bl0[2], bl0[3]);
                MMA16816(acc[2], ah, bl1[0], bl1[1]);
                MMA16816(acc[3], ah, bl1[2], bl1[3]);
                MMA16816(acc[0], al, bh0[0], bh0[1]);
                MMA16816(acc[1], al, bh0[2], bh0[3]);
                MMA16816(acc[2], al, bh1[0], bh1[1]);
                MMA16816(acc[3], al, bh1[2], bh1[3]);
            }
            if (i < 21)
                lda(ap[i % 3], ablob(t, 2 * (i + 3) + g, s), lane);
        }

        // ---- stage D to acc smem (stride 37, conflict-free) ----
        #pragma unroll
        for (int nt = 0; nt < 4; ++nt) {
            abuf[mA * ACCSTR + nt * 8 + cA]           = acc[nt][0];
            abuf[mA * ACCSTR + nt * 8 + cA + 1]       = acc[nt][1];
            abuf[(mA + 8) * ACCSTR + nt * 8 + cA]     = acc[nt][2];
            abuf[(mA + 8) * ACCSTR + nt * 8 + cA + 1] = acc[nt][3];
        }
        __syncthreads();

        // prefetch next step's first 3 x-chunks (safe: immutable)
        if (t + 1 < kT) {
            lda(ap[0], ablob(t + 1, g, s), lane);
            lda(ap[1], ablob(t + 1, 2 + g, s), lane);
            lda(ap[2], ablob(t + 1, 4 + g, s), lane);
        }

        // ---- epilogue: gates + state update (all 256 threads, 2 units each) ----
        {
            const float* a0 = (const float*)(smem + ACC0);
            const float* a1 = (const float*)(smem + ACC0 + ACCSZ);
            float hv[2];
            #pragma unroll
            for (int u = 0; u < 2; ++u) {
                int n = (ej * 2 + u) * 4;
                float sf = a0[eb * ACCSTR + n + 0] + a1[eb * ACCSTR + n + 0] + bb[u][0];
                float si = a0[eb * ACCSTR + n + 1] + a1[eb * ACCSTR + n + 1] + bb[u][1];
                float so = a0[eb * ACCSTR + n + 2] + a1[eb * ACCSTR + n + 2] + bb[u][2];
                float sg = a0[eb * ACCSTR + n + 3] + a1[eb * ACCSTR + n + 3] + bb[u][3];
                float f = sigf(sf), ii = sigf(si), o = sigf(so), gg = tanhf(sg);
                float cn = f * cs[u] + ii * gg;
                cs[u] = cn;
                hv[u] = o * tanhf(cn);
            }
            if (t < kT - 1) {
                __nv_bfloat16 h0 = __float2bfloat16(hv[0]);
                __nv_bfloat16 h1 = __float2bfloat16(hv[1]);
                __nv_bfloat162 hp; hp.x = h0; hp.y = h1;
                __nv_bfloat162 lp = __floats2bfloat162_rn(
                    hv[0] - __bfloat162float(h0), hv[1] - __bfloat162float(h1));
                unsigned char* dst = g_ht + ((size_t)(((t & 1) ^ 1) * 16) << 13)
                                   + hcsel + hoff;
                *(uint32_t*)dst          = *(uint32_t*)&hp;
                *(uint32_t*)(dst + 1024) = *(uint32_t*)&lp;
                __threadfence();
            } else {
                #pragma unroll
                for (int u = 0; u < 2; ++u) {
                    out[eb * kH + j0 + ej * 2 + u]            = hv[u];
                    out[kB * kH + eb * kH + j0 + ej * 2 + u]  = cs[u];
                }
            }
        }
        __syncthreads();
        if (t < kT - 1 && tid == 0) atomicAdd(g_arr + t, 1);
    }
}

extern "C" void kernel_launch(void* const* d_in, const int* in_sizes, int n_in,
                              void* d_out, int out_size)
{
    (void)in_sizes; (void)n_in; (void)out_size;
    const float* x  = (const float*)d_in[0];
    const float* Wf = (const float*)d_in[1];
    const float* bf = (const float*)d_in[2];
    const float* Wi = (const float*)d_in[3];
    const float* bi = (const float*)d_in[4];
    const float* Wo = (const float*)d_in[5];
    const float* bo = (const float*)d_in[6];
    const float* Wc = (const float*)d_in[7];
    const float* bc = (const float*)d_in[8];
    float* out = (float*)d_out;

    cudaFuncSetAttribute(lstm6_kernel,
                         cudaFuncAttributeMaxDynamicSharedMemorySize, SMEMB);
    lstm6_init<<<256, 256>>>();
    lstm6_xsplit<<<kT * 16, 128>>>(x);
    lstm6_kernel<<<kNCTA, kNTHR, SMEMB>>>(Wf, bf, Wi, bi, Wo, bo, Wc, bc, out);
}